// round 2
// baseline (speedup 1.0000x reference)
#include <cuda_runtime.h>
#include <cuda_bf16.h>

// BranchNet0: N=131072 rows, IN_DIM=256, HID=256, B=8 branches, C=128 classes.
// Strategy: fuse W_base into both the estimator and classifier weights once per
// launch, route rows by argmin(est), then one grouped fp32 GEMM over the
// selected branch only.

#define NROWS   131072
#define IN_DIM  256
#define HID     256
#define NB      8
#define NC      128

// Scratch (module-static device globals; no runtime allocation)
__device__ float g_Wof[NB * IN_DIM * NC];   // fused classifier weights [b][k][c] (1 MB)
__device__ float g_bof[NB * NC];            // fused classifier bias    [b][c]
__device__ float g_Wef[IN_DIM * NB];        // fused estimator weights  [k][b]
__device__ float g_bef[NB];                 // fused estimator bias
__device__ int   g_count[NB];               // rows per branch
__device__ int   g_rows[NB * NROWS];        // per-branch row lists (4 MB)

// ---------------------------------------------------------------------------
// K0a: W_of[b][k][c] = sum_h W_base[k][h] * W_clf[b][h][c]
// grid (8 k-tiles, 8 branches), 256 threads. 32-k x 128-c tile, 32-h chunks.
// ---------------------------------------------------------------------------
__global__ __launch_bounds__(256) void fuse_wof_kernel(
    const float* __restrict__ Wb, const float* __restrict__ Wclf)
{
    __shared__ float Ash[32][33];    // W_base  [k][h] chunk
    __shared__ float Bsh[32][128];   // W_clf   [h][c] chunk

    const int b  = blockIdx.y;
    const int k0 = blockIdx.x * 32;
    const int tid = threadIdx.x;
    const int c  = tid & 127;
    const int kg = tid >> 7;         // 0 or 1 -> k-half

    float acc[16];
#pragma unroll
    for (int i = 0; i < 16; i++) acc[i] = 0.f;

    for (int h0 = 0; h0 < HID; h0 += 32) {
        // load Ash: 1024 elems, 4 per thread
#pragma unroll
        for (int m = 0; m < 4; m++) {
            int idx = tid + m * 256;
            int k = idx >> 5, h = idx & 31;
            Ash[k][h] = Wb[(k0 + k) * HID + h0 + h];
        }
        // load Bsh: 4096 elems, 16 per thread (coalesced on c)
#pragma unroll
        for (int m = 0; m < 16; m++) {
            int idx = tid + m * 256;
            int h = idx >> 7, cc = idx & 127;
            Bsh[h][cc] = Wclf[((b * HID) + (h0 + h)) * NC + cc];
        }
        __syncthreads();
#pragma unroll
        for (int h = 0; h < 32; h++) {
            float bv = Bsh[h][c];
#pragma unroll
            for (int kk = 0; kk < 16; kk++)
                acc[kk] += Ash[kg * 16 + kk][h] * bv;
        }
        __syncthreads();
    }
#pragma unroll
    for (int kk = 0; kk < 16; kk++)
        g_Wof[((size_t)b * IN_DIM + (k0 + kg * 16 + kk)) * NC + c] = acc[kk];
}

// ---------------------------------------------------------------------------
// K0b: fused estimator weights/biases, classifier bias, zero counters.
// ---------------------------------------------------------------------------
__global__ void fuse_small_kernel(
    const float* __restrict__ Wb,   const float* __restrict__ bb,
    const float* __restrict__ Wclf, const float* __restrict__ bclf,
    const float* __restrict__ West, const float* __restrict__ best)
{
    const int gtid   = blockIdx.x * blockDim.x + threadIdx.x;
    const int gstride = gridDim.x * blockDim.x;

    if (gtid < NB) {
        g_count[gtid] = 0;
        float a = 0.f;
        for (int h = 0; h < HID; h++) a += bb[h] * West[gtid * HID + h];
        g_bef[gtid] = a + best[gtid];
    }
    // W_ef[k][b] = sum_h Wb[k][h] * West[b][h]
    for (int idx = gtid; idx < IN_DIM * NB; idx += gstride) {
        int k = idx >> 3, b = idx & 7;
        float a = 0.f;
        for (int h = 0; h < HID; h++) a += Wb[k * HID + h] * West[b * HID + h];
        g_Wef[k * NB + b] = a;
    }
    // b_of[b][c] = sum_h bb[h] * Wclf[b][h][c] + bclf[b][c]
    for (int idx = gtid; idx < NB * NC; idx += gstride) {
        int b = idx >> 7, c = idx & 127;
        float a = 0.f;
        for (int h = 0; h < HID; h++) a += bb[h] * Wclf[(b * HID + h) * NC + c];
        g_bof[idx] = a + bclf[idx];
    }
}

// ---------------------------------------------------------------------------
// K1: est + argmin + binning. 256 threads = 8 warps; warp handles 32 rows.
// Block handles 256 rows -> only 8 global atomics per block.
// ---------------------------------------------------------------------------
__global__ __launch_bounds__(256) void est_kernel(const float* __restrict__ x)
{
    __shared__ int scount[NB];
    __shared__ int sbase[NB];
    __shared__ int srows[NB * 256];

    const int tid  = threadIdx.x;
    const int lane = tid & 31;
    const int warp = tid >> 5;

    if (tid < NB) scount[tid] = 0;
    __syncthreads();

    float bef[NB];
#pragma unroll
    for (int b = 0; b < NB; b++) bef[b] = g_bef[b];

    const float4* wef = (const float4*)g_Wef;   // [k][b] -> 2 float4 per k
    const int rowbase = blockIdx.x * 256 + warp * 32;

    for (int i = 0; i < 32; i++) {
        const int n = rowbase + i;
        const float4* xr = (const float4*)(x + (size_t)n * IN_DIM);
        float4 va = xr[lane];
        float4 vb = xr[32 + lane];
        float av[8] = {va.x, va.y, va.z, va.w, vb.x, vb.y, vb.z, vb.w};

        float acc[NB];
#pragma unroll
        for (int b = 0; b < NB; b++) acc[b] = 0.f;

#pragma unroll
        for (int j = 0; j < 8; j++) {
            int k = (j < 4) ? (4 * lane + j) : (128 + 4 * lane + (j - 4));
            float4 w0 = wef[2 * k];
            float4 w1 = wef[2 * k + 1];
            float xv = av[j];
            acc[0] += xv * w0.x; acc[1] += xv * w0.y;
            acc[2] += xv * w0.z; acc[3] += xv * w0.w;
            acc[4] += xv * w1.x; acc[5] += xv * w1.y;
            acc[6] += xv * w1.z; acc[7] += xv * w1.w;
        }
#pragma unroll
        for (int off = 16; off; off >>= 1) {
#pragma unroll
            for (int b = 0; b < NB; b++)
                acc[b] += __shfl_xor_sync(0xffffffffu, acc[b], off);
        }
        if (lane == 0) {
            float best = acc[0] + bef[0];
            int bid = 0;
#pragma unroll
            for (int b = 1; b < NB; b++) {
                float v = acc[b] + bef[b];
                if (v < best) { best = v; bid = b; }   // first-min tie break
            }
            int lpos = atomicAdd(&scount[bid], 1);
            srows[bid * 256 + lpos] = n;
        }
    }
    __syncthreads();
    if (tid < NB) sbase[tid] = atomicAdd(&g_count[tid], scount[tid]);
    __syncthreads();
    for (int b = 0; b < NB; b++) {
        int cnt = scount[b], base = sbase[b];
        for (int i = tid; i < cnt; i += 256)
            g_rows[(size_t)b * NROWS + base + i] = srows[b * 256 + i];
    }
}

// ---------------------------------------------------------------------------
// K2: grouped GEMM. Per block: one branch, 64 gathered rows x 128 cols, K=256.
// 256 threads: warp w owns rows w*8..w*8+7, lane owns cols lane*4..lane*4+3.
// ---------------------------------------------------------------------------
__global__ __launch_bounds__(256) void gemm_kernel(
    const float* __restrict__ x, float* __restrict__ out)
{
    __shared__ float Xs[64][32];     // [row][k]   (warp-broadcast reads)
    __shared__ float Ws[32][128];    // [k][c]
    __shared__ int   sRid[64];

    const int b     = blockIdx.y;
    const int cnt   = g_count[b];
    const int tile0 = blockIdx.x * 64;
    if (tile0 >= cnt) return;

    const int tid = threadIdx.x;
    const int tc  = tid & 31;    // lane -> col group
    const int tr  = tid >> 5;    // warp -> row group

    if (tid < 64) {
        int idx = tile0 + tid;
        sRid[tid] = (idx < cnt) ? g_rows[(size_t)b * NROWS + idx] : -1;
    }
    __syncthreads();

    float4 acc[8];
#pragma unroll
    for (int r = 0; r < 8; r++) acc[r] = make_float4(0.f, 0.f, 0.f, 0.f);

    const float* wbase = g_Wof + (size_t)b * IN_DIM * NC;

    for (int k0 = 0; k0 < IN_DIM; k0 += 32) {
        // stage X: 64 rows x 32 k, gathered. float4 loads along k.
#pragma unroll
        for (int m = 0; m < 2; m++) {
            int j   = tid + m * 256;           // 0..511
            int row = j >> 3, kq = j & 7;
            int rid = sRid[row];
            int src = (rid < 0) ? 0 : rid;
            float4 v = *(const float4*)(x + (size_t)src * IN_DIM + k0 + kq * 4);
            *(float4*)&Xs[row][kq * 4] = v;
        }
        // stage W: 32 k x 128 c
#pragma unroll
        for (int m = 0; m < 4; m++) {
            int j  = tid + m * 256;            // 0..1023
            int kk = j >> 5, cq = j & 31;
            *(float4*)&Ws[kk][cq * 4] =
                *(const float4*)(wbase + (size_t)(k0 + kk) * NC + cq * 4);
        }
        __syncthreads();

#pragma unroll
        for (int kk = 0; kk < 32; kk++) {
            float4 wv = *(const float4*)&Ws[kk][tc * 4];
#pragma unroll
            for (int r = 0; r < 8; r++) {
                float xv = Xs[tr * 8 + r][kk];   // broadcast within warp
                acc[r].x += xv * wv.x;
                acc[r].y += xv * wv.y;
                acc[r].z += xv * wv.z;
                acc[r].w += xv * wv.w;
            }
        }
        __syncthreads();
    }

    float4 bias = *(const float4*)(g_bof + b * NC + tc * 4);
#pragma unroll
    for (int r = 0; r < 8; r++) {
        int rid = sRid[tr * 8 + r];
        if (rid >= 0) {
            float4 o;
            o.x = acc[r].x + bias.x;
            o.y = acc[r].y + bias.y;
            o.z = acc[r].z + bias.z;
            o.w = acc[r].w + bias.w;
            *(float4*)(out + (size_t)rid * NC + tc * 4) = o;
        }
    }
}

// ---------------------------------------------------------------------------
// launch
// ---------------------------------------------------------------------------
extern "C" void kernel_launch(void* const* d_in, const int* in_sizes, int n_in,
                              void* d_out, int out_size)
{
    const float* x     = (const float*)d_in[0];   // [N, 256]
    const float* Wb    = (const float*)d_in[1];   // [256, 256]
    const float* bb    = (const float*)d_in[2];   // [256]
    const float* Wclf  = (const float*)d_in[3];   // [8, 256, 128]
    const float* bclf  = (const float*)d_in[4];   // [8, 128]
    const float* West  = (const float*)d_in[5];   // [8, 256]
    const float* best  = (const float*)d_in[6];   // [8]
    float* out = (float*)d_out;                   // [N, 128]

    fuse_wof_kernel<<<dim3(IN_DIM / 32, NB), 256>>>(Wb, Wclf);
    fuse_small_kernel<<<16, 256>>>(Wb, bb, Wclf, bclf, West, best);
    est_kernel<<<NROWS / 256, 256>>>(x);
    gemm_kernel<<<dim3(NROWS / 64, NB), 256>>>(x, out);
}

// round 4
// speedup vs baseline: 1.7135x; 1.7135x over previous
#include <cuda_runtime.h>
#include <cuda_bf16.h>

// BranchNet0: N=131072, IN_DIM=256, HID=256, B=8, C=128.
// Fuse W_base into estimator + classifier weights; route by argmin(est);
// grouped fp32 GEMM over selected branch only, using packed fma.rn.f32x2.

#define NROWS   131072
#define IN_DIM  256
#define HID     256
#define NB      8
#define NC      128
#define TILE_M  64

__device__ float g_Wof[NB * IN_DIM * NC];   // fused classifier weights [b][k][c]
__device__ float g_bof[NB * NC];            // fused classifier bias
__device__ float g_Wef[IN_DIM * NB];        // fused estimator weights [k][b]
__device__ float g_bef[NB];
__device__ int   g_count[NB];
__device__ int   g_rows[NB * NROWS];
__device__ int   g_tilebase[NB];            // exclusive prefix of tile counts
__device__ int   g_totaltiles;

// ---- packed f32x2 helpers -------------------------------------------------
__device__ __forceinline__ void fma2(unsigned long long& d,
                                     unsigned long long a, unsigned long long b) {
    asm("fma.rn.f32x2 %0, %1, %2, %0;" : "+l"(d) : "l"(a), "l"(b));
}
__device__ __forceinline__ unsigned long long packdup(float x) {
    unsigned long long d;
    asm("mov.b64 %0, {%1, %1};" : "=l"(d) : "f"(x));
    return d;
}
__device__ __forceinline__ void unpack2(unsigned long long v, float& lo, float& hi) {
    asm("mov.b64 {%0, %1}, %2;" : "=f"(lo), "=f"(hi) : "l"(v));
}

// ---------------------------------------------------------------------------
// K0a: W_of[b][k][c] = sum_h W_base[k][h] * W_clf[b][h][c]
// grid (16 k-tiles, 8 branches), 256 threads; 16-k x 128-c tile, 32-h chunks.
// ---------------------------------------------------------------------------
__global__ __launch_bounds__(256) void fuse_wof_kernel(
    const float* __restrict__ Wb, const float* __restrict__ Wclf)
{
    __shared__ float Ash[16][33];
    __shared__ float Bsh[32][128];

    const int b  = blockIdx.y;
    const int k0 = blockIdx.x * 16;
    const int tid = threadIdx.x;
    const int c  = tid & 127;
    const int kg = tid >> 7;      // 0/1 -> 8-k half

    float acc[8];
#pragma unroll
    for (int i = 0; i < 8; i++) acc[i] = 0.f;

    for (int h0 = 0; h0 < HID; h0 += 32) {
#pragma unroll
        for (int m = 0; m < 2; m++) {
            int idx = tid + m * 256;          // 512 elems
            int k = idx >> 5, h = idx & 31;
            Ash[k][h] = Wb[(k0 + k) * HID + h0 + h];
        }
#pragma unroll
        for (int m = 0; m < 16; m++) {
            int idx = tid + m * 256;          // 4096 elems
            int h = idx >> 7, cc = idx & 127;
            Bsh[h][cc] = Wclf[((b * HID) + (h0 + h)) * NC + cc];
        }
        __syncthreads();
#pragma unroll
        for (int h = 0; h < 32; h++) {
            float bv = Bsh[h][c];
#pragma unroll
            for (int kk = 0; kk < 8; kk++)
                acc[kk] += Ash[kg * 8 + kk][h] * bv;
        }
        __syncthreads();
    }
#pragma unroll
    for (int kk = 0; kk < 8; kk++)
        g_Wof[((size_t)b * IN_DIM + (k0 + kg * 8 + kk)) * NC + c] = acc[kk];
}

// ---------------------------------------------------------------------------
// K0b: fused estimator weights/biases, classifier bias, zero counters.
// ---------------------------------------------------------------------------
__global__ void fuse_small_kernel(
    const float* __restrict__ Wb,   const float* __restrict__ bb,
    const float* __restrict__ Wclf, const float* __restrict__ bclf,
    const float* __restrict__ West, const float* __restrict__ best)
{
    const int gtid    = blockIdx.x * blockDim.x + threadIdx.x;
    const int gstride = gridDim.x * blockDim.x;

    if (gtid < NB) {
        g_count[gtid] = 0;
        float a = 0.f;
        for (int h = 0; h < HID; h++) a += bb[h] * West[gtid * HID + h];
        g_bef[gtid] = a + best[gtid];
    }
    for (int idx = gtid; idx < IN_DIM * NB; idx += gstride) {
        int k = idx >> 3, b = idx & 7;
        float a = 0.f;
        for (int h = 0; h < HID; h++) a += Wb[k * HID + h] * West[b * HID + h];
        g_Wef[k * NB + b] = a;
    }
    for (int idx = gtid; idx < NB * NC; idx += gstride) {
        int b = idx >> 7, c = idx & 127;
        float a = 0.f;
        for (int h = 0; h < HID; h++) a += bb[h] * Wclf[(b * HID + h) * NC + c];
        g_bof[idx] = a + bclf[idx];
    }
}

// ---------------------------------------------------------------------------
// K1: est + argmin + binning. 128 threads, thread-per-row, smem-staged x.
// ---------------------------------------------------------------------------
#define EST_ROWS 128
__global__ __launch_bounds__(EST_ROWS) void est_kernel(const float* __restrict__ x)
{
    __shared__ float Wef_s[IN_DIM][NB];     // 8 KB
    __shared__ float Xs[EST_ROWS][33];      // 16.5 KB, conflict-free pad
    __shared__ int scount[NB];
    __shared__ int sbase[NB];
    __shared__ int srows[NB * EST_ROWS];

    const int tid = threadIdx.x;
    const int row0 = blockIdx.x * EST_ROWS;

    // stage Wef: 2048 floats
#pragma unroll
    for (int m = 0; m < 16; m++) {
        int idx = tid + m * EST_ROWS;
        ((float*)Wef_s)[idx] = g_Wef[idx];
    }
    if (tid < NB) scount[tid] = 0;

    float bef[NB];
#pragma unroll
    for (int b = 0; b < NB; b++) bef[b] = g_bef[b];
    __syncthreads();

    float acc[NB];
#pragma unroll
    for (int b = 0; b < NB; b++) acc[b] = 0.f;

    for (int k0 = 0; k0 < IN_DIM; k0 += 32) {
        // stage 128 rows x 32 k (1024 float4 -> 8/thread)
#pragma unroll
        for (int m = 0; m < 8; m++) {
            int idx = tid + m * EST_ROWS;   // 0..1023
            int r = idx >> 3, kq = idx & 7;
            float4 v = *(const float4*)(x + (size_t)(row0 + r) * IN_DIM + k0 + kq * 4);
            Xs[r][kq * 4 + 0] = v.x;
            Xs[r][kq * 4 + 1] = v.y;
            Xs[r][kq * 4 + 2] = v.z;
            Xs[r][kq * 4 + 3] = v.w;
        }
        __syncthreads();
#pragma unroll
        for (int kk = 0; kk < 32; kk++) {
            float xv = Xs[tid][kk];
            float4 w0 = *(const float4*)&Wef_s[k0 + kk][0];   // broadcast
            float4 w1 = *(const float4*)&Wef_s[k0 + kk][4];
            acc[0] += xv * w0.x; acc[1] += xv * w0.y;
            acc[2] += xv * w0.z; acc[3] += xv * w0.w;
            acc[4] += xv * w1.x; acc[5] += xv * w1.y;
            acc[6] += xv * w1.z; acc[7] += xv * w1.w;
        }
        __syncthreads();
    }

    // argmin (first-min tie break, matches jnp.argmin)
    float best = acc[0] + bef[0];
    int bid = 0;
#pragma unroll
    for (int b = 1; b < NB; b++) {
        float v = acc[b] + bef[b];
        if (v < best) { best = v; bid = b; }
    }
    int lpos = atomicAdd(&scount[bid], 1);
    srows[bid * EST_ROWS + lpos] = row0 + tid;
    __syncthreads();

    if (tid < NB) sbase[tid] = atomicAdd(&g_count[tid], scount[tid]);
    __syncthreads();
    for (int b = 0; b < NB; b++) {
        int cnt = scount[b], base = sbase[b];
        if (tid < cnt)
            g_rows[(size_t)b * NROWS + base + tid] = srows[b * EST_ROWS + tid];
    }
}

// ---------------------------------------------------------------------------
// plan: tile prefix sums (1 block)
// ---------------------------------------------------------------------------
__global__ void plan_kernel()
{
    if (threadIdx.x == 0) {
        int acc = 0;
#pragma unroll
        for (int b = 0; b < NB; b++) {
            g_tilebase[b] = acc;
            acc += (g_count[b] + TILE_M - 1) / TILE_M;
        }
        g_totaltiles = acc;
    }
}

// ---------------------------------------------------------------------------
// K2: grouped GEMM with packed FFMA2. Flat tile grid.
// Per tile: one branch, 64 gathered rows x 128 cols, K=256.
// 256 threads: warp tr owns rows tr*8..+7 (4 row-pairs), lane tc owns 4 cols.
// ---------------------------------------------------------------------------
__global__ __launch_bounds__(256, 3) void gemm_kernel(
    const float* __restrict__ x, float* __restrict__ out)
{
    __shared__ float Xt[32][66];     // [k][row], pad 66 (even -> LDS.64 aligned)
    __shared__ float Ws[32][128];
    __shared__ int   sRid[TILE_M];

    const int flat = blockIdx.x;
    if (flat >= g_totaltiles) return;

    // find branch for this flat tile
    int b = 0;
#pragma unroll
    for (int i = 1; i < NB; i++)
        if (flat >= g_tilebase[i]) b = i;

    const int cnt   = g_count[b];
    const int tile0 = (flat - g_tilebase[b]) * TILE_M;

    const int tid = threadIdx.x;
    const int tc  = tid & 31;
    const int tr  = tid >> 5;

    if (tid < TILE_M) {
        int idx = tile0 + tid;
        sRid[tid] = (idx < cnt) ? g_rows[(size_t)b * NROWS + idx] : -1;
    }
    __syncthreads();

    unsigned long long acc2[4][4];   // [row-pair][col] packed (r_even, r_odd)
#pragma unroll
    for (int rp = 0; rp < 4; rp++)
#pragma unroll
        for (int c = 0; c < 4; c++) acc2[rp][c] = 0ULL;

    const float* wbase = g_Wof + (size_t)b * IN_DIM * NC;
    const int myrow = tr * 8;

    for (int k0 = 0; k0 < IN_DIM; k0 += 32) {
        // stage X transposed: pass p, thread -> kq = (tid>>6)+4p, row = tid&63
#pragma unroll
        for (int p = 0; p < 2; p++) {
            int kq  = (tid >> 6) + 4 * p;
            int row = tid & 63;
            int rid = sRid[row];
            int src = (rid < 0) ? 0 : rid;
            float4 v = *(const float4*)(x + (size_t)src * IN_DIM + k0 + kq * 4);
            Xt[kq * 4 + 0][row] = v.x;
            Xt[kq * 4 + 1][row] = v.y;
            Xt[kq * 4 + 2][row] = v.z;
            Xt[kq * 4 + 3][row] = v.w;
        }
        // stage W: 32 k x 128 c
#pragma unroll
        for (int m = 0; m < 4; m++) {
            int j  = tid + m * 256;
            int kk = j >> 5, cq = j & 31;
            *(float4*)&Ws[kk][cq * 4] =
                *(const float4*)(wbase + (size_t)(k0 + kk) * NC + cq * 4);
        }
        __syncthreads();

#pragma unroll
        for (int kk = 0; kk < 32; kk++) {
            float4 wv = *(const float4*)&Ws[kk][tc * 4];
            unsigned long long wd0 = packdup(wv.x);
            unsigned long long wd1 = packdup(wv.y);
            unsigned long long wd2 = packdup(wv.z);
            unsigned long long wd3 = packdup(wv.w);
            unsigned long long xp0 = *(const unsigned long long*)&Xt[kk][myrow + 0];
            unsigned long long xp1 = *(const unsigned long long*)&Xt[kk][myrow + 2];
            unsigned long long xp2 = *(const unsigned long long*)&Xt[kk][myrow + 4];
            unsigned long long xp3 = *(const unsigned long long*)&Xt[kk][myrow + 6];
            fma2(acc2[0][0], xp0, wd0); fma2(acc2[0][1], xp0, wd1);
            fma2(acc2[0][2], xp0, wd2); fma2(acc2[0][3], xp0, wd3);
            fma2(acc2[1][0], xp1, wd0); fma2(acc2[1][1], xp1, wd1);
            fma2(acc2[1][2], xp1, wd2); fma2(acc2[1][3], xp1, wd3);
            fma2(acc2[2][0], xp2, wd0); fma2(acc2[2][1], xp2, wd1);
            fma2(acc2[2][2], xp2, wd2); fma2(acc2[2][3], xp2, wd3);
            fma2(acc2[3][0], xp3, wd0); fma2(acc2[3][1], xp3, wd1);
            fma2(acc2[3][2], xp3, wd2); fma2(acc2[3][3], xp3, wd3);
        }
        __syncthreads();
    }

    float4 bias = *(const float4*)(g_bof + b * NC + tc * 4);
#pragma unroll
    for (int rp = 0; rp < 4; rp++) {
        float lo[4], hi[4];
#pragma unroll
        for (int c = 0; c < 4; c++) unpack2(acc2[rp][c], lo[c], hi[c]);
        int rid0 = sRid[myrow + 2 * rp];
        int rid1 = sRid[myrow + 2 * rp + 1];
        if (rid0 >= 0) {
            float4 o = { lo[0] + bias.x, lo[1] + bias.y, lo[2] + bias.z, lo[3] + bias.w };
            *(float4*)(out + (size_t)rid0 * NC + tc * 4) = o;
        }
        if (rid1 >= 0) {
            float4 o = { hi[0] + bias.x, hi[1] + bias.y, hi[2] + bias.z, hi[3] + bias.w };
            *(float4*)(out + (size_t)rid1 * NC + tc * 4) = o;
        }
    }
}

// ---------------------------------------------------------------------------
extern "C" void kernel_launch(void* const* d_in, const int* in_sizes, int n_in,
                              void* d_out, int out_size)
{
    const float* x     = (const float*)d_in[0];
    const float* Wb    = (const float*)d_in[1];
    const float* bb    = (const float*)d_in[2];
    const float* Wclf  = (const float*)d_in[3];
    const float* bclf  = (const float*)d_in[4];
    const float* West  = (const float*)d_in[5];
    const float* best  = (const float*)d_in[6];
    float* out = (float*)d_out;

    fuse_small_kernel<<<16, 256>>>(Wb, bb, Wclf, bclf, West, best);
    fuse_wof_kernel<<<dim3(IN_DIM / 16, NB), 256>>>(Wb, Wclf);
    est_kernel<<<NROWS / EST_ROWS, EST_ROWS>>>(x);
    plan_kernel<<<1, 32>>>();
    // worst case: all rows in one branch -> 2048 tiles + 7 empty branches
    gemm_kernel<<<NROWS / TILE_M + NB - 1, 256>>>(x, out);
}

// round 6
// speedup vs baseline: 2.2929x; 1.3382x over previous
#include <cuda_runtime.h>
#include <cuda_bf16.h>
#include <cstdint>

// BranchNet0: N=131072, IN_DIM=256, HID=256, B=8, C=128.
// Fuse W_base into estimator + classifier weights; route by argmin(est) (fp32,
// bit-identical routing); grouped GEMM over selected branch with split-bf16
// warp-level tensor cores (mma.sync m16n8k16):
//   x*w ~= xhi*whi + xhi*wlo + xlo*whi.

#define NROWS   131072
#define IN_DIM  256
#define HID     256
#define NB      8
#define NC      128
#define K_DIM   256
#define TILE_M  128
#define BK      64

__device__ float g_Wof[NB * IN_DIM * NC];   // fused classifier weights [b][k][c]
__device__ float g_bof[NB * NC];
__device__ float g_Wef[IN_DIM * NB];
__device__ float g_bef[NB];
__device__ int   g_count[NB];
__device__ int   g_rows[NB * NROWS];
__device__ int   g_tilebase[NB];
__device__ int   g_totaltiles;
// split W, pre-swizzled: per branch, per 64-k chunk: [kk][swizzled 256B row]
__device__ __align__(16) __nv_bfloat16 g_Whi[NB * K_DIM * NC];
__device__ __align__(16) __nv_bfloat16 g_Wlo[NB * K_DIM * NC];

// ---------------- helpers ---------------------------------------------------
__device__ __forceinline__ uint32_t smem_u32(const void* p) {
    uint32_t a;
    asm("{ .reg .u64 t; cvta.to.shared.u64 t, %1; cvt.u32.u64 %0, t; }"
        : "=r"(a) : "l"(p));
    return a;
}
__device__ __forceinline__ void ldmx4(uint32_t& r0, uint32_t& r1,
                                      uint32_t& r2, uint32_t& r3, uint32_t a) {
    asm volatile("ldmatrix.sync.aligned.m8n8.x4.shared.b16 {%0,%1,%2,%3}, [%4];"
                 : "=r"(r0), "=r"(r1), "=r"(r2), "=r"(r3) : "r"(a));
}
__device__ __forceinline__ void ldmx2t(uint32_t& r0, uint32_t& r1, uint32_t a) {
    asm volatile("ldmatrix.sync.aligned.m8n8.x2.trans.shared.b16 {%0,%1}, [%2];"
                 : "=r"(r0), "=r"(r1) : "r"(a));
}
__device__ __forceinline__ void mma16816(float* d, const uint32_t* a,
                                         const uint32_t* bb) {
    asm volatile("mma.sync.aligned.m16n8k16.row.col.f32.bf16.bf16.f32 "
                 "{%0,%1,%2,%3}, {%4,%5,%6,%7}, {%8,%9}, {%0,%1,%2,%3};"
                 : "+f"(d[0]), "+f"(d[1]), "+f"(d[2]), "+f"(d[3])
                 : "r"(a[0]), "r"(a[1]), "r"(a[2]), "r"(a[3]),
                   "r"(bb[0]), "r"(bb[1]));
}

// ---------------------------------------------------------------------------
// K0a: W_of[b][k][c] = sum_h W_base[k][h] * W_clf[b][h][c]   (fp32)
// ---------------------------------------------------------------------------
__global__ __launch_bounds__(256) void fuse_wof_kernel(
    const float* __restrict__ Wb, const float* __restrict__ Wclf)
{
    __shared__ float Ash[16][33];
    __shared__ float Bsh[32][128];

    const int b  = blockIdx.y;
    const int k0 = blockIdx.x * 16;
    const int tid = threadIdx.x;
    const int c  = tid & 127;
    const int kg = tid >> 7;

    float acc[8];
#pragma unroll
    for (int i = 0; i < 8; i++) acc[i] = 0.f;

    for (int h0 = 0; h0 < HID; h0 += 32) {
#pragma unroll
        for (int m = 0; m < 2; m++) {
            int idx = tid + m * 256;
            int k = idx >> 5, h = idx & 31;
            Ash[k][h] = Wb[(k0 + k) * HID + h0 + h];
        }
#pragma unroll
        for (int m = 0; m < 16; m++) {
            int idx = tid + m * 256;
            int h = idx >> 7, cc = idx & 127;
            Bsh[h][cc] = Wclf[((b * HID) + (h0 + h)) * NC + cc];
        }
        __syncthreads();
#pragma unroll
        for (int h = 0; h < 32; h++) {
            float bv = Bsh[h][c];
#pragma unroll
            for (int kk = 0; kk < 8; kk++)
                acc[kk] += Ash[kg * 8 + kk][h] * bv;
        }
        __syncthreads();
    }
#pragma unroll
    for (int kk = 0; kk < 8; kk++)
        g_Wof[((size_t)b * IN_DIM + (k0 + kg * 8 + kk)) * NC + c] = acc[kk];
}

// ---------------------------------------------------------------------------
// K0b: fused estimator weights/biases, classifier bias, zero counters.
// ---------------------------------------------------------------------------
__global__ void fuse_small_kernel(
    const float* __restrict__ Wb,   const float* __restrict__ bb,
    const float* __restrict__ Wclf, const float* __restrict__ bclf,
    const float* __restrict__ West, const float* __restrict__ best)
{
    const int gtid    = blockIdx.x * blockDim.x + threadIdx.x;
    const int gstride = gridDim.x * blockDim.x;

    if (gtid < NB) {
        g_count[gtid] = 0;
        float a = 0.f;
        for (int h = 0; h < HID; h++) a += bb[h] * West[gtid * HID + h];
        g_bef[gtid] = a + best[gtid];
    }
    for (int idx = gtid; idx < IN_DIM * NB; idx += gstride) {
        int k = idx >> 3, b = idx & 7;
        float a = 0.f;
        for (int h = 0; h < HID; h++) a += Wb[k * HID + h] * West[b * HID + h];
        g_Wef[k * NB + b] = a;
    }
    for (int idx = gtid; idx < NB * NC; idx += gstride) {
        int b = idx >> 7, c = idx & 127;
        float a = 0.f;
        for (int h = 0; h < HID; h++) a += bb[h] * Wclf[(b * HID + h) * NC + c];
        g_bof[idx] = a + bclf[idx];
    }
}

// ---------------------------------------------------------------------------
// K0c: split fp32 W_of -> (hi, lo) bf16, pre-swizzled for ldmatrix.
// Per branch layout: chunk (k>>6) * 16384B + kk*256B + ((c*2) ^ ((kk&7)<<4)).
// ---------------------------------------------------------------------------
__global__ __launch_bounds__(256) void wsplit_kernel()
{
    int idx = blockIdx.x * 256 + threadIdx.x;   // NB*K_DIM*NC = 262144
    int b = idx >> 15;
    int k = (idx >> 7) & 255;
    int c = idx & 127;
    float v = g_Wof[((size_t)b * IN_DIM + k) * NC + c];
    __nv_bfloat16 h = __float2bfloat16(v);
    __nv_bfloat16 l = __float2bfloat16(v - __bfloat162float(h));
    int chunk = k >> 6, kk = k & 63;
    uint32_t byteoff = (uint32_t)chunk * 16384 + (uint32_t)kk * 256
                     + (((uint32_t)c << 1) ^ (((uint32_t)kk & 7) << 4));
    size_t di = (size_t)b * (K_DIM * NC) + (byteoff >> 1);
    g_Whi[di] = h;
    g_Wlo[di] = l;
}

// ---------------------------------------------------------------------------
// K1: est + argmin + binning (fp32, unchanged -> routing identical).
// ---------------------------------------------------------------------------
#define EST_ROWS 128
__global__ __launch_bounds__(EST_ROWS) void est_kernel(const float* __restrict__ x)
{
    __shared__ float Wef_s[IN_DIM][NB];
    __shared__ float Xs[EST_ROWS][33];
    __shared__ int scount[NB];
    __shared__ int sbase[NB];
    __shared__ int srows[NB * EST_ROWS];

    const int tid = threadIdx.x;
    const int row0 = blockIdx.x * EST_ROWS;

#pragma unroll
    for (int m = 0; m < 16; m++) {
        int idx = tid + m * EST_ROWS;
        ((float*)Wef_s)[idx] = g_Wef[idx];
    }
    if (tid < NB) scount[tid] = 0;

    float bef[NB];
#pragma unroll
    for (int b = 0; b < NB; b++) bef[b] = g_bef[b];
    __syncthreads();

    float acc[NB];
#pragma unroll
    for (int b = 0; b < NB; b++) acc[b] = 0.f;

    for (int k0 = 0; k0 < IN_DIM; k0 += 32) {
#pragma unroll
        for (int m = 0; m < 8; m++) {
            int idx = tid + m * EST_ROWS;
            int r = idx >> 3, kq = idx & 7;
            float4 v = *(const float4*)(x + (size_t)(row0 + r) * IN_DIM + k0 + kq * 4);
            Xs[r][kq * 4 + 0] = v.x;
            Xs[r][kq * 4 + 1] = v.y;
            Xs[r][kq * 4 + 2] = v.z;
            Xs[r][kq * 4 + 3] = v.w;
        }
        __syncthreads();
#pragma unroll
        for (int kk = 0; kk < 32; kk++) {
            float xv = Xs[tid][kk];
            float4 w0 = *(const float4*)&Wef_s[k0 + kk][0];
            float4 w1 = *(const float4*)&Wef_s[k0 + kk][4];
            acc[0] += xv * w0.x; acc[1] += xv * w0.y;
            acc[2] += xv * w0.z; acc[3] += xv * w0.w;
            acc[4] += xv * w1.x; acc[5] += xv * w1.y;
            acc[6] += xv * w1.z; acc[7] += xv * w1.w;
        }
        __syncthreads();
    }

    float best = acc[0] + bef[0];
    int bid = 0;
#pragma unroll
    for (int b = 1; b < NB; b++) {
        float v = acc[b] + bef[b];
        if (v < best) { best = v; bid = b; }
    }
    int lpos = atomicAdd(&scount[bid], 1);
    srows[bid * EST_ROWS + lpos] = row0 + tid;
    __syncthreads();

    if (tid < NB) sbase[tid] = atomicAdd(&g_count[tid], scount[tid]);
    __syncthreads();
    for (int b = 0; b < NB; b++) {
        int cnt = scount[b], base = sbase[b];
        if (tid < cnt)
            g_rows[(size_t)b * NROWS + base + tid] = srows[b * EST_ROWS + tid];
    }
}

// ---------------------------------------------------------------------------
__global__ void plan_kernel()
{
    if (threadIdx.x == 0) {
        int acc = 0;
#pragma unroll
        for (int b = 0; b < NB; b++) {
            g_tilebase[b] = acc;
            acc += (g_count[b] + TILE_M - 1) / TILE_M;
        }
        g_totaltiles = acc;
    }
}

// ---------------------------------------------------------------------------
// K2: split-bf16 mma.sync grouped GEMM.
// Tile: 128 rows x 128 cols x K=256, BK=64 chunks.
// 8 warps in 4(m) x 2(n) grid; warp = 32 rows x 64 cols via m16n8k16.
// SMEM (dyn, 1KB-aligned): Xhi 16K | Xlo 16K | Whi 16K | Wlo 16K.
//   X rows: 128B (64 bf16), swizzle: byte ^ ((row&7)<<4)
//   W rows: 256B (128 bf16), same swizzle on kk.
// ---------------------------------------------------------------------------
#define SMEM_DYN (65536 + 1024)

__global__ __launch_bounds__(256, 2) void gemm_kernel(
    const float* __restrict__ x, float* __restrict__ out)
{
    extern __shared__ char dsm[];
    __shared__ int sRid[TILE_M];

    const int flat = blockIdx.x;
    if (flat >= g_totaltiles) return;

    int b = 0;
#pragma unroll
    for (int i = 1; i < NB; i++)
        if (flat >= g_tilebase[i]) b = i;
    const int cnt   = g_count[b];
    const int tile0 = (flat - g_tilebase[b]) * TILE_M;

    const int tid    = threadIdx.x;
    const int wid    = tid >> 5;
    const int lane   = tid & 31;
    const int warp_m = wid & 3;
    const int warp_n = wid >> 2;

    const uint32_t dsm_u = smem_u32(dsm);
    const uint32_t base  = (dsm_u + 1023) & ~1023u;
    char* basep = dsm + (base - dsm_u);
    const uint32_t Xhi_u = base, Xlo_u = base + 16384;
    const uint32_t Whi_u = base + 32768, Wlo_u = base + 49152;

    if (tid < TILE_M) {
        int idx = tile0 + tid;
        sRid[tid] = (idx < cnt) ? g_rows[(size_t)b * NROWS + idx] : -1;
    }
    __syncthreads();

    // staging identities
    const int srow   = tid >> 1;             // 0..127 (X) / reuse for W: tid>>1 covers 0..127 but W has 64 rows
    const int skhalf = (tid & 1) * 32;       // X: 32 k per thread
    const int srid   = sRid[srow];
    const float* xrow = x + (size_t)((srid < 0) ? 0 : srid) * IN_DIM;
    const uint32_t sxor = ((uint32_t)srow & 7) << 4;

    // per-warp fragment addresses
    const int rowA   = warp_m * 32 + (lane & 15);
    const uint32_t rowAbyte = (uint32_t)rowA * 128;
    const uint32_t xorA = ((uint32_t)rowA & 7) << 4;
    const uint32_t segA = ((uint32_t)lane >> 4) * 16;
    const int rowBl  = lane & 15;
    const uint32_t xorB = ((uint32_t)rowBl & 7) << 4;
    uint32_t colB[8];
#pragma unroll
    for (int nf = 0; nf < 8; nf++)
        colB[nf] = (((uint32_t)warp_n * 128 + (uint32_t)nf * 16) ^ xorB);

    float acc[2][8][4];
#pragma unroll
    for (int mf = 0; mf < 2; mf++)
#pragma unroll
        for (int nf = 0; nf < 8; nf++)
#pragma unroll
            for (int q = 0; q < 4; q++) acc[mf][nf][q] = 0.f;

    const uint4* gwh = (const uint4*)(g_Whi + (size_t)b * K_DIM * NC);
    const uint4* gwl = (const uint4*)(g_Wlo + (size_t)b * K_DIM * NC);

    for (int ch = 0; ch < 4; ch++) {
        // ---- stage X: convert row srow, k = ch*64 + skhalf .. +32 ----
        {
            const float4* xs = (const float4*)(xrow + ch * 64 + skhalf);
            char* dh = basep;            // Xhi
            char* dl = basep + 16384;    // Xlo
            uint32_t rb = (uint32_t)srow * 128;
#pragma unroll
            for (int j = 0; j < 8; j++) {
                float4 v = xs[j];
                uint32_t h0, h1, l0, l1;
                asm("cvt.rn.bf16x2.f32 %0, %1, %2;" : "=r"(h0) : "f"(v.y), "f"(v.x));
                asm("cvt.rn.bf16x2.f32 %0, %1, %2;" : "=r"(h1) : "f"(v.w), "f"(v.z));
                float a0 = v.x - __uint_as_float(h0 << 16);
                float a1 = v.y - __uint_as_float(h0 & 0xffff0000u);
                float a2 = v.z - __uint_as_float(h1 << 16);
                float a3 = v.w - __uint_as_float(h1 & 0xffff0000u);
                asm("cvt.rn.bf16x2.f32 %0, %1, %2;" : "=r"(l0) : "f"(a1), "f"(a0));
                asm("cvt.rn.bf16x2.f32 %0, %1, %2;" : "=r"(l1) : "f"(a3), "f"(a2));
                uint32_t kb = ((uint32_t)(skhalf + j * 4) << 1);   // byte of k
                uint32_t o0 = rb + ((kb + 0) ^ sxor);
                uint32_t o1 = rb + ((kb + 4) ^ sxor);
                *(uint32_t*)(dh + o0) = h0;
                *(uint32_t*)(dh + o1) = h1;
                *(uint32_t*)(dl + o0) = l0;
                *(uint32_t*)(dl + o1) = l1;
            }
        }
        // ---- stage W: flat 16KB copy per split (pre-swizzled) ----
        {
            uint4* dh = (uint4*)(basep + 32768);
            uint4* dl = (uint4*)(basep + 49152);
            const uint4* sh = gwh + ch * 1024;
            const uint4* sl = gwl + ch * 1024;
#pragma unroll
            for (int m = 0; m < 4; m++) dh[tid + m * 256] = sh[tid + m * 256];
#pragma unroll
            for (int m = 0; m < 4; m++) dl[tid + m * 256] = sl[tid + m * 256];
        }
        __syncthreads();

        // ---- compute ----
#pragma unroll
        for (int kf = 0; kf < 4; kf++) {
            uint32_t colA = ((uint32_t)kf * 32 + segA) ^ xorA;
            uint32_t ah[2][4], al[2][4];
            ldmx4(ah[0][0], ah[0][1], ah[0][2], ah[0][3],
                  Xhi_u + rowAbyte + colA);
            ldmx4(ah[1][0], ah[1][1], ah[1][2], ah[1][3],
                  Xhi_u + rowAbyte + 16 * 128 + colA);
            ldmx4(al[0][0], al[0][1], al[0][2], al[0][3],
                  Xlo_u + rowAbyte + colA);
            ldmx4(al[1][0], al[1][1], al[1][2], al[1][3],
                  Xlo_u + rowAbyte + 16 * 128 + colA);
            uint32_t rowBbyte = (uint32_t)(kf * 16 + rowBl) * 256;
#pragma unroll
            for (int nf = 0; nf < 8; nf++) {
                uint32_t bh[2], bl[2];
                ldmx2t(bh[0], bh[1], Whi_u + rowBbyte + colB[nf]);
                ldmx2t(bl[0], bl[1], Wlo_u + rowBbyte + colB[nf]);
                mma16816(acc[0][nf], ah[0], bh);
                mma16816(acc[1][nf], ah[1], bh);
                mma16816(acc[0][nf], ah[0], bl);
                mma16816(acc[1][nf], ah[1], bl);
                mma16816(acc[0][nf], al[0], bh);
                mma16816(acc[1][nf], al[1], bh);
            }
        }
        __syncthreads();
    }

    // ---- epilogue ----
    const int erow = warp_m * 32 + (lane >> 2);
    const int ecol0 = warp_n * 64 + 2 * (lane & 3);
#pragma unroll
    for (int mf = 0; mf < 2; mf++) {
        int r0 = erow + mf * 16;
        int rid0 = sRid[r0];
        int rid1 = sRid[r0 + 8];
#pragma unroll
        for (int nf = 0; nf < 8; nf++) {
            int col = ecol0 + nf * 8;
            float2 bias = *(const float2*)(g_bof + b * NC + col);
            if (rid0 >= 0) {
                float2 o = { acc[mf][nf][0] + bias.x, acc[mf][nf][1] + bias.y };
                *(float2*)(out + (size_t)rid0 * NC + col) = o;
            }
            if (rid1 >= 0) {
                float2 o = { acc[mf][nf][2] + bias.x, acc[mf][nf][3] + bias.y };
                *(float2*)(out + (size_t)rid1 * NC + col) = o;
            }
        }
    }
}

// ---------------------------------------------------------------------------
extern "C" void kernel_launch(void* const* d_in, const int* in_sizes, int n_in,
                              void* d_out, int out_size)
{
    const float* x     = (const float*)d_in[0];
    const float* Wb    = (const float*)d_in[1];
    const float* bb    = (const float*)d_in[2];
    const float* Wclf  = (const float*)d_in[3];
    const float* bclf  = (const float*)d_in[4];
    const float* West  = (const float*)d_in[5];
    const float* best  = (const float*)d_in[6];
    float* out = (float*)d_out;

    cudaFuncSetAttribute(gemm_kernel,
                         cudaFuncAttributeMaxDynamicSharedMemorySize, SMEM_DYN);

    fuse_small_kernel<<<16, 256>>>(Wb, bb, Wclf, bclf, West, best);
    fuse_wof_kernel<<<dim3(IN_DIM / 16, NB), 256>>>(Wb, Wclf);
    wsplit_kernel<<<NB * K_DIM * NC / 256, 256>>>();
    est_kernel<<<NROWS / EST_ROWS, EST_ROWS>>>(x);
    plan_kernel<<<1, 32>>>();
    gemm_kernel<<<NROWS / TILE_M + NB - 1, 256, SMEM_DYN>>>(x, out);
}